// round 9
// baseline (speedup 1.0000x reference)
#include <cuda_runtime.h>
#include <cuda_fp16.h>
#include <stdint.h>

#define IN_SIZE  4096
#define OUT_SIZE 4096
#define BATCH    256

#define BK      64                 // k-elements per stage (fp16: 128B rows)
#define NSTAGE  (IN_SIZE / BK)     // 64
#define STAGES  4
#define A_BYTES 8192               // 64 rows x 128B
#define B_BYTES 16384              // 128 rows x 128B
#define STAGE_BYTES (A_BYTES + B_BYTES)
#define SMEM_BYTES (STAGES * STAGE_BYTES)

// fp16 transposed weight g_Wh[out][in] (K-major rows), fp16 X.
__device__ __half g_Wh[(size_t)IN_SIZE * OUT_SIZE];
__device__ __half g_Xh[(size_t)BATCH * IN_SIZE];
__device__ int    g_idx_is64;

// ---------------------------------------------------------------------------
// helpers
// ---------------------------------------------------------------------------
__device__ __forceinline__ uint32_t smem_u32(const void* p) {
    uint32_t a;
    asm("{ .reg .u64 t; cvta.to.shared.u64 t, %1; cvt.u32.u64 %0, t; }"
        : "=r"(a) : "l"(p));
    return a;
}
__device__ __forceinline__ void cpa16(uint32_t s, const void* g) {
    asm volatile("cp.async.cg.shared.global [%0], [%1], 16;" :: "r"(s), "l"(g));
}
__device__ __forceinline__ void cpa_commit() {
    asm volatile("cp.async.commit_group;" ::: "memory");
}
template <int N>
__device__ __forceinline__ void cpa_wait() {
    asm volatile("cp.async.wait_group %0;" :: "n"(N) : "memory");
}
__device__ __forceinline__ void ldsm_x4(uint32_t& r0, uint32_t& r1,
                                        uint32_t& r2, uint32_t& r3, uint32_t a) {
    asm volatile("ldmatrix.sync.aligned.m8n8.x4.shared.b16 {%0,%1,%2,%3}, [%4];"
                 : "=r"(r0), "=r"(r1), "=r"(r2), "=r"(r3) : "r"(a));
}
__device__ __forceinline__ void mma_f16(float& d0, float& d1, float& d2, float& d3,
                                        uint32_t a0, uint32_t a1, uint32_t a2, uint32_t a3,
                                        uint32_t b0, uint32_t b1) {
    asm volatile(
        "mma.sync.aligned.m16n8k16.row.col.f32.f16.f16.f32 "
        "{%0,%1,%2,%3}, {%4,%5,%6,%7}, {%8,%9}, {%0,%1,%2,%3};"
        : "+f"(d0), "+f"(d1), "+f"(d2), "+f"(d3)
        : "r"(a0), "r"(a1), "r"(a2), "r"(a3), "r"(b0), "r"(b1));
}

// ---------------------------------------------------------------------------
// Zero Wh (32 MB) + fused idx dtype detection (block 0).
// ---------------------------------------------------------------------------
__global__ void zero_w_detect_kernel(const uint32_t* __restrict__ idx_words) {
    size_t i = (size_t)blockIdx.x * blockDim.x + threadIdx.x;
    reinterpret_cast<float4*>(g_Wh)[i] = make_float4(0.f, 0.f, 0.f, 0.f);
    if (blockIdx.x == 0 && threadIdx.x == 0) {
        uint32_t acc = 0;
#pragma unroll
        for (int j = 0; j < 64; ++j) acc |= idx_words[2 * j + 1];
        g_idx_is64 = (acc == 0u) ? 1 : 0;
    }
}

// ---------------------------------------------------------------------------
// Scatter: g_Wh[col][row] += fp16(val), native f16 atomics. 4 entries/thread.
// ---------------------------------------------------------------------------
__global__ void scatter_kernel(const void* __restrict__ idx,
                               const float* __restrict__ val,
                               int nnz) {
    const int base = (blockIdx.x * blockDim.x + threadIdx.x) * 4;
    if (base >= nnz) return;
    const int is64 = g_idx_is64;

    if (base + 4 <= nnz) {
        float4 v4 = *reinterpret_cast<const float4*>(val + base);
        float v[4] = {v4.x, v4.y, v4.z, v4.w};
        int row[4], col[4];
        if (is64) {
            const longlong2* p = reinterpret_cast<const longlong2*>(idx) + base;
            longlong2 e0 = p[0], e1 = p[1], e2 = p[2], e3 = p[3];
            row[0] = (int)e0.x; col[0] = (int)e0.y;
            row[1] = (int)e1.x; col[1] = (int)e1.y;
            row[2] = (int)e2.x; col[2] = (int)e2.y;
            row[3] = (int)e3.x; col[3] = (int)e3.y;
        } else {
            const int4* p = reinterpret_cast<const int4*>(idx) + base / 2;
            int4 e0 = p[0], e1 = p[1];
            row[0] = e0.x; col[0] = e0.y;
            row[1] = e0.z; col[1] = e0.w;
            row[2] = e1.x; col[2] = e1.y;
            row[3] = e1.z; col[3] = e1.w;
        }
#pragma unroll
        for (int j = 0; j < 4; ++j)
            atomicAdd(&g_Wh[(size_t)col[j] * IN_SIZE + row[j]], __float2half_rn(v[j]));
    } else {
        for (int i = base; i < nnz; ++i) {
            int row, col;
            if (is64) {
                longlong2 p = reinterpret_cast<const longlong2*>(idx)[i];
                row = (int)p.x; col = (int)p.y;
            } else {
                int2 p = reinterpret_cast<const int2*>(idx)[i];
                row = p.x; col = p.y;
            }
            atomicAdd(&g_Wh[(size_t)col * IN_SIZE + row], __float2half_rn(val[i]));
        }
    }
}

// ---------------------------------------------------------------------------
// X -> fp16
// ---------------------------------------------------------------------------
__global__ void cvt_x_kernel(const float* __restrict__ X) {
    size_t i = (size_t)blockIdx.x * blockDim.x + threadIdx.x;
    float4 v = reinterpret_cast<const float4*>(X)[i];
    __half2 h0 = __floats2half2_rn(v.x, v.y);
    __half2 h1 = __floats2half2_rn(v.z, v.w);
    reinterpret_cast<__half2*>(g_Xh)[2 * i + 0] = h0;
    reinterpret_cast<__half2*>(g_Xh)[2 * i + 1] = h1;
}

// ---------------------------------------------------------------------------
// fp16 mma.sync GEMM v7: out = relu(X @ Wh^T + bias)
//
// CTA 64(M) x 128(N), 128 threads = 4 warps (2m x 2n), warp tile 32x64.
// m16n8k16 fp16 MMA, fp32 accumulate. K staged 64/iter (128B rows, 64 fp16),
// 64 stages, 4-stage cp.async pipeline, one sync per stage.
// Per warp per k16-step: 2 ldsm_x4 (A msubs) + 4 ldsm_x4 (B nsub-pairs) + 16 HMMA.
//
// SMEM per stage: A 64x128B then B 128x128B, chunk swizzle:
//   byte_off(row, kchunk) = row*128 + ((kchunk ^ (row&7)) << 4)
// (identical addressing to the validated tf32 v5 kernel; fp16 fragments are the
//  natural ldmatrix.b16 case.)
// ---------------------------------------------------------------------------
__global__ __launch_bounds__(128, 1)
void gemm_f16_mma(const float* __restrict__ bias, float* __restrict__ out) {
    extern __shared__ uint32_t smu[];
    const uint32_t sbase0 = smem_u32(smu);

    const int tid   = threadIdx.x;
    const int lane  = tid & 31;
    const int wid   = tid >> 5;
    const int warpm = wid & 1;          // 0..1 -> 32 rows
    const int warpn = wid >> 1;         // 0..1 -> 64 cols
    const int m0 = blockIdx.y * 64;
    const int n0 = blockIdx.x * 128;

    // staging: srow 0..15, sj 0..7 (16B chunk = 8 fp16)
    const int srow = tid >> 3;
    const int sj   = tid & 7;

    const __half* Ag = g_Xh + (size_t)(m0 + srow) * IN_SIZE + sj * 8;
    const __half* Bg = g_Wh + (size_t)(n0 + srow) * IN_SIZE + sj * 8;

    const uint32_t swz = (uint32_t)((sj ^ (srow & 7)) << 4);
    uint32_t offA[4], offB[8];
#pragma unroll
    for (int i = 0; i < 4; ++i)
        offA[i] = (uint32_t)((srow + 16 * i) * 128) + swz;
#pragma unroll
    for (int i = 0; i < 8; ++i)
        offB[i] = A_BYTES + (uint32_t)((srow + 16 * i) * 128) + swz;

    // ldmatrix lane-address components (same mapping as v5)
    const int l7 = lane & 7;
    const int qa = lane >> 4;            // A k-quad select (mats 2,3)
    const int qb = (lane >> 3) & 1;      // B k-quad select
    uint32_t rAbase[2];
#pragma unroll
    for (int msub = 0; msub < 2; ++msub)
        rAbase[msub] = (uint32_t)((warpm * 32 + msub * 16 +
                                   ((lane >> 3) & 1) * 8 + l7) * 128);
    uint32_t rBbase[4];
#pragma unroll
    for (int p = 0; p < 4; ++p)
        rBbase[p] = (uint32_t)((warpn * 64 + p * 16 + ((lane >> 4) << 3) + l7) * 128);

    float acc[2][8][4];
#pragma unroll
    for (int a = 0; a < 2; ++a)
#pragma unroll
        for (int b = 0; b < 8; ++b)
#pragma unroll
            for (int d = 0; d < 4; ++d) acc[a][b][d] = 0.f;

    // ---- prologue: issue stages 0..2
#pragma unroll
    for (int ps = 0; ps < 3; ++ps) {
        const uint32_t sb = sbase0 + (uint32_t)ps * STAGE_BYTES;
#pragma unroll
        for (int i = 0; i < 4; ++i)
            cpa16(sb + offA[i], Ag + (size_t)(16 * i) * IN_SIZE + ps * BK);
#pragma unroll
        for (int i = 0; i < 8; ++i)
            cpa16(sb + offB[i], Bg + (size_t)(16 * i) * IN_SIZE + ps * BK);
        cpa_commit();
    }

    for (int s = 0; s < NSTAGE; ++s) {
        cpa_wait<2>();
        __syncthreads();   // stage s visible AND stage s-1 compute done

        if (s + 3 < NSTAGE) {
            const uint32_t nb = sbase0 + (uint32_t)((s + 3) & 3) * STAGE_BYTES;
            const int ko = (s + 3) * BK;
#pragma unroll
            for (int i = 0; i < 4; ++i)
                cpa16(nb + offA[i], Ag + (size_t)(16 * i) * IN_SIZE + ko);
#pragma unroll
            for (int i = 0; i < 8; ++i)
                cpa16(nb + offB[i], Bg + (size_t)(16 * i) * IN_SIZE + ko);
        }
        cpa_commit();

        const uint32_t sb = sbase0 + (uint32_t)(s & 3) * STAGE_BYTES;
#pragma unroll
        for (int ks = 0; ks < 4; ++ks) {         // 4 x k16 per 64-wide stage
            const uint32_t aswz = (uint32_t)(((ks * 2 + qa) ^ l7) << 4);
            const uint32_t bswz = (uint32_t)(((ks * 2 + qb) ^ l7) << 4);
            uint32_t af[2][4];
#pragma unroll
            for (int msub = 0; msub < 2; ++msub)
                ldsm_x4(af[msub][0], af[msub][1], af[msub][2], af[msub][3],
                        sb + rAbase[msub] + aswz);
            uint32_t bf[8][2];
#pragma unroll
            for (int p = 0; p < 4; ++p)
                ldsm_x4(bf[2 * p][0], bf[2 * p][1], bf[2 * p + 1][0], bf[2 * p + 1][1],
                        sb + A_BYTES + rBbase[p] + bswz);
#pragma unroll
            for (int msub = 0; msub < 2; ++msub)
#pragma unroll
                for (int nsub = 0; nsub < 8; ++nsub)
                    mma_f16(acc[msub][nsub][0], acc[msub][nsub][1],
                            acc[msub][nsub][2], acc[msub][nsub][3],
                            af[msub][0], af[msub][1], af[msub][2], af[msub][3],
                            bf[nsub][0], bf[nsub][1]);
        }
    }

    // ---- epilogue: bias + relu, float2 stores (same m16n8 acc mapping)
#pragma unroll
    for (int msub = 0; msub < 2; ++msub) {
        const int m = m0 + warpm * 32 + msub * 16 + (lane >> 2);
#pragma unroll
        for (int nsub = 0; nsub < 8; ++nsub) {
            const int n = n0 + warpn * 64 + nsub * 8 + (lane & 3) * 2;
            float2 bv = *reinterpret_cast<const float2*>(bias + n);
            float2 o0, o1;
            o0.x = fmaxf(acc[msub][nsub][0] + bv.x, 0.f);
            o0.y = fmaxf(acc[msub][nsub][1] + bv.y, 0.f);
            o1.x = fmaxf(acc[msub][nsub][2] + bv.x, 0.f);
            o1.y = fmaxf(acc[msub][nsub][3] + bv.y, 0.f);
            *reinterpret_cast<float2*>(out + (size_t)m * OUT_SIZE + n)       = o0;
            *reinterpret_cast<float2*>(out + (size_t)(m + 8) * OUT_SIZE + n) = o1;
        }
    }
}

// ---------------------------------------------------------------------------
// kernel_launch
// ---------------------------------------------------------------------------
extern "C" void kernel_launch(void* const* d_in, const int* in_sizes, int n_in,
                              void* d_out, int out_size) {
    const float* X    = (const float*)d_in[0];
    const void*  idx  = d_in[1];
    const float* val  = (const float*)d_in[2];
    const float* bias = (const float*)d_in[3];
    float*       out  = (float*)d_out;

    const int nnz = in_sizes[2];

    // zero 32 MB of fp16 W (float4 = 8 halfs): 16M halfs / 8 / 256 = 8192 blocks
    zero_w_detect_kernel<<<(int)(((size_t)IN_SIZE * OUT_SIZE / 8) / 256), 256>>>(
        (const uint32_t*)idx);
    scatter_kernel<<<(nnz / 4 + 255) / 256, 256>>>(idx, val, nnz);
    cvt_x_kernel<<<(int)(((size_t)BATCH * IN_SIZE / 4) / 256), 256>>>(X);

    cudaFuncSetAttribute(gemm_f16_mma,
                         cudaFuncAttributeMaxDynamicSharedMemorySize, SMEM_BYTES);
    dim3 grid(OUT_SIZE / 128, BATCH / 64);   // (32, 4) = 128 CTAs
    gemm_f16_mma<<<grid, 128, SMEM_BYTES>>>(bias, out);
}

// round 11
// speedup vs baseline: 1.8558x; 1.8558x over previous
#include <cuda_runtime.h>
#include <cuda_fp16.h>
#include <stdint.h>

#define IN_SIZE  4096
#define OUT_SIZE 4096
#define BATCH    256

#define BK      64                 // k-elements per stage (fp16: 128B rows)
#define NSTAGE  (IN_SIZE / BK)     // 64
#define STAGES  4
#define A_BYTES 8192               // 64 rows x 128B
#define B_BYTES 16384              // 128 rows x 128B
#define STAGE_BYTES (A_BYTES + B_BYTES)
#define SMEM_BYTES (STAGES * STAGE_BYTES)

// fp32 scatter target (transposed W), then converted to fp16 for the GEMM.
__device__ float  g_Wt[(size_t)IN_SIZE * OUT_SIZE];
__device__ __half g_Wh[(size_t)IN_SIZE * OUT_SIZE];
__device__ __half g_Xh[(size_t)BATCH * IN_SIZE];
__device__ int    g_idx_is64;

// ---------------------------------------------------------------------------
// helpers
// ---------------------------------------------------------------------------
__device__ __forceinline__ uint32_t smem_u32(const void* p) {
    uint32_t a;
    asm("{ .reg .u64 t; cvta.to.shared.u64 t, %1; cvt.u32.u64 %0, t; }"
        : "=r"(a) : "l"(p));
    return a;
}
__device__ __forceinline__ void cpa16(uint32_t s, const void* g) {
    asm volatile("cp.async.cg.shared.global [%0], [%1], 16;" :: "r"(s), "l"(g));
}
__device__ __forceinline__ void cpa_commit() {
    asm volatile("cp.async.commit_group;" ::: "memory");
}
template <int N>
__device__ __forceinline__ void cpa_wait() {
    asm volatile("cp.async.wait_group %0;" :: "n"(N) : "memory");
}
__device__ __forceinline__ void ldsm_x4(uint32_t& r0, uint32_t& r1,
                                        uint32_t& r2, uint32_t& r3, uint32_t a) {
    asm volatile("ldmatrix.sync.aligned.m8n8.x4.shared.b16 {%0,%1,%2,%3}, [%4];"
                 : "=r"(r0), "=r"(r1), "=r"(r2), "=r"(r3) : "r"(a));
}
__device__ __forceinline__ void mma_f16(float& d0, float& d1, float& d2, float& d3,
                                        uint32_t a0, uint32_t a1, uint32_t a2, uint32_t a3,
                                        uint32_t b0, uint32_t b1) {
    asm volatile(
        "mma.sync.aligned.m16n8k16.row.col.f32.f16.f16.f32 "
        "{%0,%1,%2,%3}, {%4,%5,%6,%7}, {%8,%9}, {%0,%1,%2,%3};"
        : "+f"(d0), "+f"(d1), "+f"(d2), "+f"(d3)
        : "r"(a0), "r"(a1), "r"(a2), "r"(a3), "r"(b0), "r"(b1));
}
__device__ __forceinline__ uint32_t h2_bits(__half2 h) {
    union { __half2 h; uint32_t u; } c;
    c.h = h;
    return c.u;
}

// ---------------------------------------------------------------------------
// Zero fp32 Wt (64 MB) + fused idx dtype detection (block 0).
// ---------------------------------------------------------------------------
__global__ void zero_w_detect_kernel(const uint32_t* __restrict__ idx_words) {
    size_t i = (size_t)blockIdx.x * blockDim.x + threadIdx.x;
    reinterpret_cast<float4*>(g_Wt)[i] = make_float4(0.f, 0.f, 0.f, 0.f);
    if (blockIdx.x == 0 && threadIdx.x == 0) {
        uint32_t acc = 0;
#pragma unroll
        for (int j = 0; j < 64; ++j) acc |= idx_words[2 * j + 1];
        g_idx_is64 = (acc == 0u) ? 1 : 0;
    }
}

// ---------------------------------------------------------------------------
// Scatter: g_Wt[col][row] += fp32(fp16-rounded val). Native fp32 REDG atomics.
// Single-hit cells become exact fp16 after the cvt pass.
// ---------------------------------------------------------------------------
__global__ void scatter_kernel(const void* __restrict__ idx,
                               const float* __restrict__ val,
                               int nnz) {
    const int base = (blockIdx.x * blockDim.x + threadIdx.x) * 4;
    if (base >= nnz) return;
    const int is64 = g_idx_is64;

    if (base + 4 <= nnz) {
        float4 v4 = *reinterpret_cast<const float4*>(val + base);
        float v[4] = {v4.x, v4.y, v4.z, v4.w};
        int row[4], col[4];
        if (is64) {
            const longlong2* p = reinterpret_cast<const longlong2*>(idx) + base;
            longlong2 e0 = p[0], e1 = p[1], e2 = p[2], e3 = p[3];
            row[0] = (int)e0.x; col[0] = (int)e0.y;
            row[1] = (int)e1.x; col[1] = (int)e1.y;
            row[2] = (int)e2.x; col[2] = (int)e2.y;
            row[3] = (int)e3.x; col[3] = (int)e3.y;
        } else {
            const int4* p = reinterpret_cast<const int4*>(idx) + base / 2;
            int4 e0 = p[0], e1 = p[1];
            row[0] = e0.x; col[0] = e0.y;
            row[1] = e0.z; col[1] = e0.w;
            row[2] = e1.x; col[2] = e1.y;
            row[3] = e1.z; col[3] = e1.w;
        }
#pragma unroll
        for (int j = 0; j < 4; ++j) {
            float w = __half2float(__float2half_rn(v[j]));
            atomicAdd(&g_Wt[(size_t)col[j] * IN_SIZE + row[j]], w);
        }
    } else {
        for (int i = base; i < nnz; ++i) {
            int row, col;
            if (is64) {
                longlong2 p = reinterpret_cast<const longlong2*>(idx)[i];
                row = (int)p.x; col = (int)p.y;
            } else {
                int2 p = reinterpret_cast<const int2*>(idx)[i];
                row = p.x; col = p.y;
            }
            float w = __half2float(__float2half_rn(val[i]));
            atomicAdd(&g_Wt[(size_t)col * IN_SIZE + row], w);
        }
    }
}

// ---------------------------------------------------------------------------
// W fp32 -> fp16 (96 MB traffic)
// ---------------------------------------------------------------------------
__global__ void cvt_w_kernel() {
    size_t i = (size_t)blockIdx.x * blockDim.x + threadIdx.x;
    float4 v0 = reinterpret_cast<const float4*>(g_Wt)[2 * i + 0];
    float4 v1 = reinterpret_cast<const float4*>(g_Wt)[2 * i + 1];
    uint4 o;
    o.x = h2_bits(__floats2half2_rn(v0.x, v0.y));
    o.y = h2_bits(__floats2half2_rn(v0.z, v0.w));
    o.z = h2_bits(__floats2half2_rn(v1.x, v1.y));
    o.w = h2_bits(__floats2half2_rn(v1.z, v1.w));
    reinterpret_cast<uint4*>(g_Wh)[i] = o;
}

// ---------------------------------------------------------------------------
// X -> fp16
// ---------------------------------------------------------------------------
__global__ void cvt_x_kernel(const float* __restrict__ X) {
    size_t i = (size_t)blockIdx.x * blockDim.x + threadIdx.x;
    float4 v = reinterpret_cast<const float4*>(X)[i];
    __half2 h0 = __floats2half2_rn(v.x, v.y);
    __half2 h1 = __floats2half2_rn(v.z, v.w);
    reinterpret_cast<__half2*>(g_Xh)[2 * i + 0] = h0;
    reinterpret_cast<__half2*>(g_Xh)[2 * i + 1] = h1;
}

// ---------------------------------------------------------------------------
// fp16 mma.sync GEMM (validated v7): out = relu(X @ Wh^T + bias)
// CTA 64x128, 128 threads = 4 warps (2m x 2n), warp tile 32x64.
// m16n8k16, K staged 64/iter, 64 stages, 4-stage cp.async pipeline.
// ---------------------------------------------------------------------------
__global__ __launch_bounds__(128, 1)
void gemm_f16_mma(const float* __restrict__ bias, float* __restrict__ out) {
    extern __shared__ uint32_t smu[];
    const uint32_t sbase0 = smem_u32(smu);

    const int tid   = threadIdx.x;
    const int lane  = tid & 31;
    const int wid   = tid >> 5;
    const int warpm = wid & 1;
    const int warpn = wid >> 1;
    const int m0 = blockIdx.y * 64;
    const int n0 = blockIdx.x * 128;

    const int srow = tid >> 3;
    const int sj   = tid & 7;

    const __half* Ag = g_Xh + (size_t)(m0 + srow) * IN_SIZE + sj * 8;
    const __half* Bg = g_Wh + (size_t)(n0 + srow) * IN_SIZE + sj * 8;

    const uint32_t swz = (uint32_t)((sj ^ (srow & 7)) << 4);
    uint32_t offA[4], offB[8];
#pragma unroll
    for (int i = 0; i < 4; ++i)
        offA[i] = (uint32_t)((srow + 16 * i) * 128) + swz;
#pragma unroll
    for (int i = 0; i < 8; ++i)
        offB[i] = A_BYTES + (uint32_t)((srow + 16 * i) * 128) + swz;

    const int l7 = lane & 7;
    const int qa = lane >> 4;
    const int qb = (lane >> 3) & 1;
    uint32_t rAbase[2];
#pragma unroll
    for (int msub = 0; msub < 2; ++msub)
        rAbase[msub] = (uint32_t)((warpm * 32 + msub * 16 +
                                   ((lane >> 3) & 1) * 8 + l7) * 128);
    uint32_t rBbase[4];
#pragma unroll
    for (int p = 0; p < 4; ++p)
        rBbase[p] = (uint32_t)((warpn * 64 + p * 16 + ((lane >> 4) << 3) + l7) * 128);

    float acc[2][8][4];
#pragma unroll
    for (int a = 0; a < 2; ++a)
#pragma unroll
        for (int b = 0; b < 8; ++b)
#pragma unroll
            for (int d = 0; d < 4; ++d) acc[a][b][d] = 0.f;

#pragma unroll
    for (int ps = 0; ps < 3; ++ps) {
        const uint32_t sb = sbase0 + (uint32_t)ps * STAGE_BYTES;
#pragma unroll
        for (int i = 0; i < 4; ++i)
            cpa16(sb + offA[i], Ag + (size_t)(16 * i) * IN_SIZE + ps * BK);
#pragma unroll
        for (int i = 0; i < 8; ++i)
            cpa16(sb + offB[i], Bg + (size_t)(16 * i) * IN_SIZE + ps * BK);
        cpa_commit();
    }

    for (int s = 0; s < NSTAGE; ++s) {
        cpa_wait<2>();
        __syncthreads();

        if (s + 3 < NSTAGE) {
            const uint32_t nb = sbase0 + (uint32_t)((s + 3) & 3) * STAGE_BYTES;
            const int ko = (s + 3) * BK;
#pragma unroll
            for (int i = 0; i < 4; ++i)
                cpa16(nb + offA[i], Ag + (size_t)(16 * i) * IN_SIZE + ko);
#pragma unroll
            for (int i = 0; i < 8; ++i)
                cpa16(nb + offB[i], Bg + (size_t)(16 * i) * IN_SIZE + ko);
        }
        cpa_commit();

        const uint32_t sb = sbase0 + (uint32_t)(s & 3) * STAGE_BYTES;
#pragma unroll
        for (int ks = 0; ks < 4; ++ks) {
            const uint32_t aswz = (uint32_t)(((ks * 2 + qa) ^ l7) << 4);
            const uint32_t bswz = (uint32_t)(((ks * 2 + qb) ^ l7) << 4);
            uint32_t af[2][4];
#pragma unroll
            for (int msub = 0; msub < 2; ++msub)
                ldsm_x4(af[msub][0], af[msub][1], af[msub][2], af[msub][3],
                        sb + rAbase[msub] + aswz);
            uint32_t bf[8][2];
#pragma unroll
            for (int p = 0; p < 4; ++p)
                ldsm_x4(bf[2 * p][0], bf[2 * p][1], bf[2 * p + 1][0], bf[2 * p + 1][1],
                        sb + A_BYTES + rBbase[p] + bswz);
#pragma unroll
            for (int msub = 0; msub < 2; ++msub)
#pragma unroll
                for (int nsub = 0; nsub < 8; ++nsub)
                    mma_f16(acc[msub][nsub][0], acc[msub][nsub][1],
                            acc[msub][nsub][2], acc[msub][nsub][3],
                            af[msub][0], af[msub][1], af[msub][2], af[msub][3],
                            bf[nsub][0], bf[nsub][1]);
        }
    }

#pragma unroll
    for (int msub = 0; msub < 2; ++msub) {
        const int m = m0 + warpm * 32 + msub * 16 + (lane >> 2);
#pragma unroll
        for (int nsub = 0; nsub < 8; ++nsub) {
            const int n = n0 + warpn * 64 + nsub * 8 + (lane & 3) * 2;
            float2 bv = *reinterpret_cast<const float2*>(bias + n);
            float2 o0, o1;
            o0.x = fmaxf(acc[msub][nsub][0] + bv.x, 0.f);
            o0.y = fmaxf(acc[msub][nsub][1] + bv.y, 0.f);
            o1.x = fmaxf(acc[msub][nsub][2] + bv.x, 0.f);
            o1.y = fmaxf(acc[msub][nsub][3] + bv.y, 0.f);
            *reinterpret_cast<float2*>(out + (size_t)m * OUT_SIZE + n)       = o0;
            *reinterpret_cast<float2*>(out + (size_t)(m + 8) * OUT_SIZE + n) = o1;
        }
    }
}

// ---------------------------------------------------------------------------
// kernel_launch
// ---------------------------------------------------------------------------
extern "C" void kernel_launch(void* const* d_in, const int* in_sizes, int n_in,
                              void* d_out, int out_size) {
    const float* X    = (const float*)d_in[0];
    const void*  idx  = d_in[1];
    const float* val  = (const float*)d_in[2];
    const float* bias = (const float*)d_in[3];
    float*       out  = (float*)d_out;

    const int nnz = in_sizes[2];

    // zero 64 MB fp32 W: 16M floats / 4 / 256 = 16384 blocks
    zero_w_detect_kernel<<<(int)(((size_t)IN_SIZE * OUT_SIZE / 4) / 256), 256>>>(
        (const uint32_t*)idx);
    scatter_kernel<<<(nnz / 4 + 255) / 256, 256>>>(idx, val, nnz);
    // cvt W: 16M elems / 8 per thread / 256 = 8192 blocks
    cvt_w_kernel<<<(int)(((size_t)IN_SIZE * OUT_SIZE / 8) / 256), 256>>>();
    cvt_x_kernel<<<(int)(((size_t)BATCH * IN_SIZE / 4) / 256), 256>>>(X);

    cudaFuncSetAttribute(gemm_f16_mma,
                         cudaFuncAttributeMaxDynamicSharedMemorySize, SMEM_BYTES);
    dim3 grid(OUT_SIZE / 128, BATCH / 64);   // (32, 4) = 128 CTAs
    gemm_f16_mma<<<grid, 128, SMEM_BYTES>>>(bias, out);
}

// round 12
// speedup vs baseline: 1.9315x; 1.0408x over previous
#include <cuda_runtime.h>
#include <cuda_fp16.h>
#include <stdint.h>

#define IN_SIZE  4096
#define OUT_SIZE 4096
#define BATCH    256

#define BK      64                 // k-elements per stage (fp16: 128B rows)
#define NSTAGE  (IN_SIZE / BK)     // 64
#define STAGES  4
#define A_BYTES 8192               // 64 rows x 128B
#define B_BYTES 16384              // 128 rows x 128B
#define STAGE_BYTES (A_BYTES + B_BYTES)
#define SMEM_BYTES (STAGES * STAGE_BYTES)

// fp16 transposed weight g_Wh[out][in] — scattered into directly via f16x2 red.
__device__ __half g_Wh[(size_t)IN_SIZE * OUT_SIZE];
__device__ __half g_Xh[(size_t)BATCH * IN_SIZE];
__device__ int    g_idx_is64;

// ---------------------------------------------------------------------------
// helpers
// ---------------------------------------------------------------------------
__device__ __forceinline__ uint32_t smem_u32(const void* p) {
    uint32_t a;
    asm("{ .reg .u64 t; cvta.to.shared.u64 t, %1; cvt.u32.u64 %0, t; }"
        : "=r"(a) : "l"(p));
    return a;
}
__device__ __forceinline__ void cpa16(uint32_t s, const void* g) {
    asm volatile("cp.async.cg.shared.global [%0], [%1], 16;" :: "r"(s), "l"(g));
}
__device__ __forceinline__ void cpa_commit() {
    asm volatile("cp.async.commit_group;" ::: "memory");
}
template <int N>
__device__ __forceinline__ void cpa_wait() {
    asm volatile("cp.async.wait_group %0;" :: "n"(N) : "memory");
}
__device__ __forceinline__ void ldsm_x4(uint32_t& r0, uint32_t& r1,
                                        uint32_t& r2, uint32_t& r3, uint32_t a) {
    asm volatile("ldmatrix.sync.aligned.m8n8.x4.shared.b16 {%0,%1,%2,%3}, [%4];"
                 : "=r"(r0), "=r"(r1), "=r"(r2), "=r"(r3) : "r"(a));
}
__device__ __forceinline__ void mma_f16(float& d0, float& d1, float& d2, float& d3,
                                        uint32_t a0, uint32_t a1, uint32_t a2, uint32_t a3,
                                        uint32_t b0, uint32_t b1) {
    asm volatile(
        "mma.sync.aligned.m16n8k16.row.col.f32.f16.f16.f32 "
        "{%0,%1,%2,%3}, {%4,%5,%6,%7}, {%8,%9}, {%0,%1,%2,%3};"
        : "+f"(d0), "+f"(d1), "+f"(d2), "+f"(d3)
        : "r"(a0), "r"(a1), "r"(a2), "r"(a3), "r"(b0), "r"(b1));
}

// ---------------------------------------------------------------------------
// Zero fp16 Wh (32 MB) + fused idx dtype detection (block 0).
// ---------------------------------------------------------------------------
__global__ void zero_w_detect_kernel(const uint32_t* __restrict__ idx_words) {
    size_t i = (size_t)blockIdx.x * blockDim.x + threadIdx.x;
    reinterpret_cast<float4*>(g_Wh)[i] = make_float4(0.f, 0.f, 0.f, 0.f);
    if (blockIdx.x == 0 && threadIdx.x == 0) {
        uint32_t acc = 0;
#pragma unroll
        for (int j = 0; j < 64; ++j) acc |= idx_words[2 * j + 1];
        g_idx_is64 = (acc == 0u) ? 1 : 0;
    }
}

// ---------------------------------------------------------------------------
// Scatter: g_Wh[col][row] += fp16(val), via NATIVE f16x2 red at the aligned
// 32-bit word (neighbor lane adds +0.0 = identity). 8 entries per thread.
// ---------------------------------------------------------------------------
__device__ __forceinline__ void scat1(int row, int col, float v) {
    const size_t cell = (size_t)col * IN_SIZE + row;
    __half2* word = reinterpret_cast<__half2*>(
        reinterpret_cast<uintptr_t>(g_Wh + cell) & ~(uintptr_t)2);
    const __half hv = __float2half_rn(v);
    const __half hz = __ushort_as_half(0);
    const __half2 add = (cell & 1) ? __halves2half2(hz, hv)
                                   : __halves2half2(hv, hz);
    atomicAdd(word, add);
}

__global__ void scatter_kernel(const void* __restrict__ idx,
                               const float* __restrict__ val,
                               int nnz) {
    const int base = (blockIdx.x * blockDim.x + threadIdx.x) * 8;
    if (base >= nnz) return;
    const int is64 = g_idx_is64;

    if (base + 8 <= nnz) {
        float4 va = *reinterpret_cast<const float4*>(val + base);
        float4 vb = *reinterpret_cast<const float4*>(val + base + 4);
        float v[8] = {va.x, va.y, va.z, va.w, vb.x, vb.y, vb.z, vb.w};
        int row[8], col[8];
        if (is64) {
            const longlong2* p = reinterpret_cast<const longlong2*>(idx) + base;
#pragma unroll
            for (int j = 0; j < 8; ++j) {
                longlong2 e = p[j];
                row[j] = (int)e.x;
                col[j] = (int)e.y;
            }
        } else {
            const int4* p = reinterpret_cast<const int4*>(idx) + base / 2;
#pragma unroll
            for (int j = 0; j < 4; ++j) {
                int4 e = p[j];
                row[2 * j]     = e.x; col[2 * j]     = e.y;
                row[2 * j + 1] = e.z; col[2 * j + 1] = e.w;
            }
        }
#pragma unroll
        for (int j = 0; j < 8; ++j) scat1(row[j], col[j], v[j]);
    } else {
        for (int i = base; i < nnz; ++i) {
            int row, col;
            if (is64) {
                longlong2 p = reinterpret_cast<const longlong2*>(idx)[i];
                row = (int)p.x; col = (int)p.y;
            } else {
                int2 p = reinterpret_cast<const int2*>(idx)[i];
                row = p.x; col = p.y;
            }
            scat1(row, col, val[i]);
        }
    }
}

// ---------------------------------------------------------------------------
// X -> fp16
// ---------------------------------------------------------------------------
__global__ void cvt_x_kernel(const float* __restrict__ X) {
    size_t i = (size_t)blockIdx.x * blockDim.x + threadIdx.x;
    float4 v = reinterpret_cast<const float4*>(X)[i];
    __half2 h0 = __floats2half2_rn(v.x, v.y);
    __half2 h1 = __floats2half2_rn(v.z, v.w);
    reinterpret_cast<__half2*>(g_Xh)[2 * i + 0] = h0;
    reinterpret_cast<__half2*>(g_Xh)[2 * i + 1] = h1;
}

// ---------------------------------------------------------------------------
// fp16 mma.sync GEMM (validated): out = relu(X @ Wh^T + bias)
// CTA 64x128, 128 threads = 4 warps (2m x 2n), warp tile 32x64.
// m16n8k16, K staged 64/iter, 64 stages, 4-stage cp.async pipeline.
// ---------------------------------------------------------------------------
__global__ __launch_bounds__(128, 1)
void gemm_f16_mma(const float* __restrict__ bias, float* __restrict__ out) {
    extern __shared__ uint32_t smu[];
    const uint32_t sbase0 = smem_u32(smu);

    const int tid   = threadIdx.x;
    const int lane  = tid & 31;
    const int wid   = tid >> 5;
    const int warpm = wid & 1;
    const int warpn = wid >> 1;
    const int m0 = blockIdx.y * 64;
    const int n0 = blockIdx.x * 128;

    const int srow = tid >> 3;
    const int sj   = tid & 7;

    const __half* Ag = g_Xh + (size_t)(m0 + srow) * IN_SIZE + sj * 8;
    const __half* Bg = g_Wh + (size_t)(n0 + srow) * IN_SIZE + sj * 8;

    const uint32_t swz = (uint32_t)((sj ^ (srow & 7)) << 4);
    uint32_t offA[4], offB[8];
#pragma unroll
    for (int i = 0; i < 4; ++i)
        offA[i] = (uint32_t)((srow + 16 * i) * 128) + swz;
#pragma unroll
    for (int i = 0; i < 8; ++i)
        offB[i] = A_BYTES + (uint32_t)((srow + 16 * i) * 128) + swz;

    const int l7 = lane & 7;
    const int qa = lane >> 4;
    const int qb = (lane >> 3) & 1;
    uint32_t rAbase[2];
#pragma unroll
    for (int msub = 0; msub < 2; ++msub)
        rAbase[msub] = (uint32_t)((warpm * 32 + msub * 16 +
                                   ((lane >> 3) & 1) * 8 + l7) * 128);
    uint32_t rBbase[4];
#pragma unroll
    for (int p = 0; p < 4; ++p)
        rBbase[p] = (uint32_t)((warpn * 64 + p * 16 + ((lane >> 4) << 3) + l7) * 128);

    float acc[2][8][4];
#pragma unroll
    for (int a = 0; a < 2; ++a)
#pragma unroll
        for (int b = 0; b < 8; ++b)
#pragma unroll
            for (int d = 0; d < 4; ++d) acc[a][b][d] = 0.f;

#pragma unroll
    for (int ps = 0; ps < 3; ++ps) {
        const uint32_t sb = sbase0 + (uint32_t)ps * STAGE_BYTES;
#pragma unroll
        for (int i = 0; i < 4; ++i)
            cpa16(sb + offA[i], Ag + (size_t)(16 * i) * IN_SIZE + ps * BK);
#pragma unroll
        for (int i = 0; i < 8; ++i)
            cpa16(sb + offB[i], Bg + (size_t)(16 * i) * IN_SIZE + ps * BK);
        cpa_commit();
    }

    for (int s = 0; s < NSTAGE; ++s) {
        cpa_wait<2>();
        __syncthreads();

        if (s + 3 < NSTAGE) {
            const uint32_t nb = sbase0 + (uint32_t)((s + 3) & 3) * STAGE_BYTES;
            const int ko = (s + 3) * BK;
#pragma unroll
            for (int i = 0; i < 4; ++i)
                cpa16(nb + offA[i], Ag + (size_t)(16 * i) * IN_SIZE + ko);
#pragma unroll
            for (int i = 0; i < 8; ++i)
                cpa16(nb + offB[i], Bg + (size_t)(16 * i) * IN_SIZE + ko);
        }
        cpa_commit();

        const uint32_t sb = sbase0 + (uint32_t)(s & 3) * STAGE_BYTES;
#pragma unroll
        for (int ks = 0; ks < 4; ++ks) {
            const uint32_t aswz = (uint32_t)(((ks * 2 + qa) ^ l7) << 4);
            const uint32_t bswz = (uint32_t)(((ks * 2 + qb) ^ l7) << 4);
            uint32_t af[2][4];
#pragma unroll
            for (int msub = 0; msub < 2; ++msub)
                ldsm_x4(af[msub][0], af[msub][1], af[msub][2], af[msub][3],
                        sb + rAbase[msub] + aswz);
            uint32_t bf[8][2];
#pragma unroll
            for (int p = 0; p < 4; ++p)
                ldsm_x4(bf[2 * p][0], bf[2 * p][1], bf[2 * p + 1][0], bf[2 * p + 1][1],
                        sb + A_BYTES + rBbase[p] + bswz);
#pragma unroll
            for (int msub = 0; msub < 2; ++msub)
#pragma unroll
                for (int nsub = 0; nsub < 8; ++nsub)
                    mma_f16(acc[msub][nsub][0], acc[msub][nsub][1],
                            acc[msub][nsub][2], acc[msub][nsub][3],
                            af[msub][0], af[msub][1], af[msub][2], af[msub][3],
                            bf[nsub][0], bf[nsub][1]);
        }
    }

#pragma unroll
    for (int msub = 0; msub < 2; ++msub) {
        const int m = m0 + warpm * 32 + msub * 16 + (lane >> 2);
#pragma unroll
        for (int nsub = 0; nsub < 8; ++nsub) {
            const int n = n0 + warpn * 64 + nsub * 8 + (lane & 3) * 2;
            float2 bv = *reinterpret_cast<const float2*>(bias + n);
            float2 o0, o1;
            o0.x = fmaxf(acc[msub][nsub][0] + bv.x, 0.f);
            o0.y = fmaxf(acc[msub][nsub][1] + bv.y, 0.f);
            o1.x = fmaxf(acc[msub][nsub][2] + bv.x, 0.f);
            o1.y = fmaxf(acc[msub][nsub][3] + bv.y, 0.f);
            *reinterpret_cast<float2*>(out + (size_t)m * OUT_SIZE + n)       = o0;
            *reinterpret_cast<float2*>(out + (size_t)(m + 8) * OUT_SIZE + n) = o1;
        }
    }
}

// ---------------------------------------------------------------------------
// kernel_launch
// ---------------------------------------------------------------------------
extern "C" void kernel_launch(void* const* d_in, const int* in_sizes, int n_in,
                              void* d_out, int out_size) {
    const float* X    = (const float*)d_in[0];
    const void*  idx  = d_in[1];
    const float* val  = (const float*)d_in[2];
    const float* bias = (const float*)d_in[3];
    float*       out  = (float*)d_out;

    const int nnz = in_sizes[2];

    // zero 32 MB fp16 W: 16M halfs / 8 per thread / 256 = 8192 blocks
    zero_w_detect_kernel<<<(int)(((size_t)IN_SIZE * OUT_SIZE / 8) / 256), 256>>>(
        (const uint32_t*)idx);
    scatter_kernel<<<(nnz / 8 + 255) / 256, 256>>>(idx, val, nnz);
    cvt_x_kernel<<<(int)(((size_t)BATCH * IN_SIZE / 4) / 256), 256>>>(X);

    cudaFuncSetAttribute(gemm_f16_mma,
                         cudaFuncAttributeMaxDynamicSharedMemorySize, SMEM_BYTES);
    dim3 grid(OUT_SIZE / 128, BATCH / 64);   // (32, 4) = 128 CTAs
    gemm_f16_mma<<<grid, 128, SMEM_BYTES>>>(bias, out);
}

// round 13
// speedup vs baseline: 1.9578x; 1.0136x over previous
#include <cuda_runtime.h>
#include <cuda_fp16.h>
#include <stdint.h>

#define IN_SIZE  4096
#define OUT_SIZE 4096
#define BATCH    256

#define BK      64                 // k-elements per stage (fp16: 128B rows)
#define NSTAGE  (IN_SIZE / BK)     // 64
#define STAGES  4
#define A_BYTES 8192               // 64 rows x 128B
#define B_BYTES 16384              // 128 rows x 128B
#define STAGE_BYTES (A_BYTES + B_BYTES)
#define SMEM_BYTES (STAGES * STAGE_BYTES)

#define ZERO_BLOCKS 8192           // 32 MB / (256 thr * 16 B)
#define CVTX_BLOCKS 1024           // 4 MB fp32 in / (256 thr * 16 B out)

// fp16 transposed weight g_Wh[out][in] — scattered into directly via f16x2 red.
__device__ __half g_Wh[(size_t)IN_SIZE * OUT_SIZE];
__device__ __half g_Xh[(size_t)BATCH * IN_SIZE];
__device__ int    g_idx_is64;

// ---------------------------------------------------------------------------
// helpers
// ---------------------------------------------------------------------------
__device__ __forceinline__ uint32_t smem_u32(const void* p) {
    uint32_t a;
    asm("{ .reg .u64 t; cvta.to.shared.u64 t, %1; cvt.u32.u64 %0, t; }"
        : "=r"(a) : "l"(p));
    return a;
}
__device__ __forceinline__ void cpa16(uint32_t s, const void* g) {
    asm volatile("cp.async.cg.shared.global [%0], [%1], 16;" :: "r"(s), "l"(g));
}
__device__ __forceinline__ void cpa_commit() {
    asm volatile("cp.async.commit_group;" ::: "memory");
}
template <int N>
__device__ __forceinline__ void cpa_wait() {
    asm volatile("cp.async.wait_group %0;" :: "n"(N) : "memory");
}
__device__ __forceinline__ void ldsm_x4(uint32_t& r0, uint32_t& r1,
                                        uint32_t& r2, uint32_t& r3, uint32_t a) {
    asm volatile("ldmatrix.sync.aligned.m8n8.x4.shared.b16 {%0,%1,%2,%3}, [%4];"
                 : "=r"(r0), "=r"(r1), "=r"(r2), "=r"(r3) : "r"(a));
}
__device__ __forceinline__ void mma_f16(float& d0, float& d1, float& d2, float& d3,
                                        uint32_t a0, uint32_t a1, uint32_t a2, uint32_t a3,
                                        uint32_t b0, uint32_t b1) {
    asm volatile(
        "mma.sync.aligned.m16n8k16.row.col.f32.f16.f16.f32 "
        "{%0,%1,%2,%3}, {%4,%5,%6,%7}, {%8,%9}, {%0,%1,%2,%3};"
        : "+f"(d0), "+f"(d1), "+f"(d2), "+f"(d3)
        : "r"(a0), "r"(a1), "r"(a2), "r"(a3), "r"(b0), "r"(b1));
}

// ---------------------------------------------------------------------------
// Fused prep: zero fp16 Wh (32 MB) + cvt X->fp16 + idx dtype detection.
// Blocks [0, ZERO_BLOCKS) zero W; blocks [ZERO_BLOCKS, +CVTX_BLOCKS) cvt X.
// ---------------------------------------------------------------------------
__global__ void prep_kernel(const uint32_t* __restrict__ idx_words,
                            const float* __restrict__ X) {
    const int b = blockIdx.x;
    if (b < ZERO_BLOCKS) {
        size_t i = (size_t)b * blockDim.x + threadIdx.x;
        reinterpret_cast<float4*>(g_Wh)[i] = make_float4(0.f, 0.f, 0.f, 0.f);
        if (b == 0 && threadIdx.x == 0) {
            uint32_t acc = 0;
#pragma unroll
            for (int j = 0; j < 64; ++j) acc |= idx_words[2 * j + 1];
            g_idx_is64 = (acc == 0u) ? 1 : 0;
        }
    } else {
        size_t i = (size_t)(b - ZERO_BLOCKS) * blockDim.x + threadIdx.x;
        float4 v = reinterpret_cast<const float4*>(X)[i];
        __half2 h0 = __floats2half2_rn(v.x, v.y);
        __half2 h1 = __floats2half2_rn(v.z, v.w);
        reinterpret_cast<__half2*>(g_Xh)[2 * i + 0] = h0;
        reinterpret_cast<__half2*>(g_Xh)[2 * i + 1] = h1;
    }
}

// ---------------------------------------------------------------------------
// Scatter: g_Wh[col][row] += fp16(val), via native f16x2 red on the aligned
// 32-bit word. 32-bit-only address/pack math (~5 ALU ops per entry):
//   cell = col*4096 + row; bits = f16(v) << ((cell&1)*16); word = cell>>1.
// The neighbor lane receives +0.0 (fp16 additive identity).
// ---------------------------------------------------------------------------
__device__ __forceinline__ void scat1(uint32_t row, uint32_t col, float v) {
    const uint32_t cell = col * (uint32_t)IN_SIZE + row;
    const uint32_t hv   = (uint32_t)__half_as_ushort(__float2half_rn(v));
    union { uint32_t u; __half2 h; } c;
    c.u = hv << ((cell & 1u) << 4);
    atomicAdd(reinterpret_cast<__half2*>(g_Wh) + (cell >> 1), c.h);
}

__global__ void scatter_kernel(const void* __restrict__ idx,
                               const float* __restrict__ val,
                               int nnz) {
    const int base = (blockIdx.x * blockDim.x + threadIdx.x) * 8;
    if (base >= nnz) return;
    const int is64 = g_idx_is64;

    if (base + 8 <= nnz) {
        float4 va = *reinterpret_cast<const float4*>(val + base);
        float4 vb = *reinterpret_cast<const float4*>(val + base + 4);
        float v[8] = {va.x, va.y, va.z, va.w, vb.x, vb.y, vb.z, vb.w};
        uint32_t row[8], col[8];
        if (is64) {
            const longlong2* p = reinterpret_cast<const longlong2*>(idx) + base;
#pragma unroll
            for (int j = 0; j < 8; ++j) {
                longlong2 e = p[j];
                row[j] = (uint32_t)e.x;
                col[j] = (uint32_t)e.y;
            }
        } else {
            const int4* p = reinterpret_cast<const int4*>(idx) + base / 2;
#pragma unroll
            for (int j = 0; j < 4; ++j) {
                int4 e = p[j];
                row[2 * j]     = (uint32_t)e.x; col[2 * j]     = (uint32_t)e.y;
                row[2 * j + 1] = (uint32_t)e.z; col[2 * j + 1] = (uint32_t)e.w;
            }
        }
#pragma unroll
        for (int j = 0; j < 8; ++j) scat1(row[j], col[j], v[j]);
    } else {
        for (int i = base; i < nnz; ++i) {
            uint32_t row, col;
            if (is64) {
                longlong2 p = reinterpret_cast<const longlong2*>(idx)[i];
                row = (uint32_t)p.x; col = (uint32_t)p.y;
            } else {
                int2 p = reinterpret_cast<const int2*>(idx)[i];
                row = (uint32_t)p.x; col = (uint32_t)p.y;
            }
            scat1(row, col, val[i]);
        }
    }
}

// ---------------------------------------------------------------------------
// fp16 mma.sync GEMM (validated): out = relu(X @ Wh^T + bias)
// CTA 64x128, 128 threads = 4 warps (2m x 2n), warp tile 32x64.
// m16n8k16, K staged 64/iter, 64 stages, 4-stage cp.async pipeline.
// ---------------------------------------------------------------------------
__global__ __launch_bounds__(128, 1)
void gemm_f16_mma(const float* __restrict__ bias, float* __restrict__ out) {
    extern __shared__ uint32_t smu[];
    const uint32_t sbase0 = smem_u32(smu);

    const int tid   = threadIdx.x;
    const int lane  = tid & 31;
    const int wid   = tid >> 5;
    const int warpm = wid & 1;
    const int warpn = wid >> 1;
    const int m0 = blockIdx.y * 64;
    const int n0 = blockIdx.x * 128;

    const int srow = tid >> 3;
    const int sj   = tid & 7;

    const __half* Ag = g_Xh + (size_t)(m0 + srow) * IN_SIZE + sj * 8;
    const __half* Bg = g_Wh + (size_t)(n0 + srow) * IN_SIZE + sj * 8;

    const uint32_t swz = (uint32_t)((sj ^ (srow & 7)) << 4);
    uint32_t offA[4], offB[8];
#pragma unroll
    for (int i = 0; i < 4; ++i)
        offA[i] = (uint32_t)((srow + 16 * i) * 128) + swz;
#pragma unroll
    for (int i = 0; i < 8; ++i)
        offB[i] = A_BYTES + (uint32_t)((srow + 16 * i) * 128) + swz;

    const int l7 = lane & 7;
    const int qa = lane >> 4;
    const int qb = (lane >> 3) & 1;
    uint32_t rAbase[2];
#pragma unroll
    for (int msub = 0; msub < 2; ++msub)
        rAbase[msub] = (uint32_t)((warpm * 32 + msub * 16 +
                                   ((lane >> 3) & 1) * 8 + l7) * 128);
    uint32_t rBbase[4];
#pragma unroll
    for (int p = 0; p < 4; ++p)
        rBbase[p] = (uint32_t)((warpn * 64 + p * 16 + ((lane >> 4) << 3) + l7) * 128);

    float acc[2][8][4];
#pragma unroll
    for (int a = 0; a < 2; ++a)
#pragma unroll
        for (int b = 0; b < 8; ++b)
#pragma unroll
            for (int d = 0; d < 4; ++d) acc[a][b][d] = 0.f;

#pragma unroll
    for (int ps = 0; ps < 3; ++ps) {
        const uint32_t sb = sbase0 + (uint32_t)ps * STAGE_BYTES;
#pragma unroll
        for (int i = 0; i < 4; ++i)
            cpa16(sb + offA[i], Ag + (size_t)(16 * i) * IN_SIZE + ps * BK);
#pragma unroll
        for (int i = 0; i < 8; ++i)
            cpa16(sb + offB[i], Bg + (size_t)(16 * i) * IN_SIZE + ps * BK);
        cpa_commit();
    }

    for (int s = 0; s < NSTAGE; ++s) {
        cpa_wait<2>();
        __syncthreads();

        if (s + 3 < NSTAGE) {
            const uint32_t nb = sbase0 + (uint32_t)((s + 3) & 3) * STAGE_BYTES;
            const int ko = (s + 3) * BK;
#pragma unroll
            for (int i = 0; i < 4; ++i)
                cpa16(nb + offA[i], Ag + (size_t)(16 * i) * IN_SIZE + ko);
#pragma unroll
            for (int i = 0; i < 8; ++i)
                cpa16(nb + offB[i], Bg + (size_t)(16 * i) * IN_SIZE + ko);
        }
        cpa_commit();

        const uint32_t sb = sbase0 + (uint32_t)(s & 3) * STAGE_BYTES;
#pragma unroll
        for (int ks = 0; ks < 4; ++ks) {
            const uint32_t aswz = (uint32_t)(((ks * 2 + qa) ^ l7) << 4);
            const uint32_t bswz = (uint32_t)(((ks * 2 + qb) ^ l7) << 4);
            uint32_t af[2][4];
#pragma unroll
            for (int msub = 0; msub < 2; ++msub)
                ldsm_x4(af[msub][0], af[msub][1], af[msub][2], af[msub][3],
                        sb + rAbase[msub] + aswz);
            uint32_t bf[8][2];
#pragma unroll
            for (int p = 0; p < 4; ++p)
                ldsm_x4(bf[2 * p][0], bf[2 * p][1], bf[2 * p + 1][0], bf[2 * p + 1][1],
                        sb + A_BYTES + rBbase[p] + bswz);
#pragma unroll
            for (int msub = 0; msub < 2; ++msub)
#pragma unroll
                for (int nsub = 0; nsub < 8; ++nsub)
                    mma_f16(acc[msub][nsub][0], acc[msub][nsub][1],
                            acc[msub][nsub][2], acc[msub][nsub][3],
                            af[msub][0], af[msub][1], af[msub][2], af[msub][3],
                            bf[nsub][0], bf[nsub][1]);
        }
    }

#pragma unroll
    for (int msub = 0; msub < 2; ++msub) {
        const int m = m0 + warpm * 32 + msub * 16 + (lane >> 2);
#pragma unroll
        for (int nsub = 0; nsub < 8; ++nsub) {
            const int n = n0 + warpn * 64 + nsub * 8 + (lane & 3) * 2;
            float2 bv = *reinterpret_cast<const float2*>(bias + n);
            float2 o0, o1;
            o0.x = fmaxf(acc[msub][nsub][0] + bv.x, 0.f);
            o0.y = fmaxf(acc[msub][nsub][1] + bv.y, 0.f);
            o1.x = fmaxf(acc[msub][nsub][2] + bv.x, 0.f);
            o1.y = fmaxf(acc[msub][nsub][3] + bv.y, 0.f);
            *reinterpret_cast<float2*>(out + (size_t)m * OUT_SIZE + n)       = o0;
            *reinterpret_cast<float2*>(out + (size_t)(m + 8) * OUT_SIZE + n) = o1;
        }
    }
}

// ---------------------------------------------------------------------------
// kernel_launch
// ---------------------------------------------------------------------------
extern "C" void kernel_launch(void* const* d_in, const int* in_sizes, int n_in,
                              void* d_out, int out_size) {
    const float* X    = (const float*)d_in[0];
    const void*  idx  = d_in[1];
    const float* val  = (const float*)d_in[2];
    const float* bias = (const float*)d_in[3];
    float*       out  = (float*)d_out;

    const int nnz = in_sizes[2];

    prep_kernel<<<ZERO_BLOCKS + CVTX_BLOCKS, 256>>>((const uint32_t*)idx, X);
    scatter_kernel<<<(nnz / 8 + 255) / 256, 256>>>(idx, val, nnz);

    cudaFuncSetAttribute(gemm_f16_mma,
                         cudaFuncAttributeMaxDynamicSharedMemorySize, SMEM_BYTES);
    dim3 grid(OUT_SIZE / 128, BATCH / 64);   // (32, 4) = 128 CTAs
    gemm_f16_mma<<<grid, 128, SMEM_BYTES>>>(bias, out);
}

// round 14
// speedup vs baseline: 2.4894x; 1.2715x over previous
#include <cuda_runtime.h>
#include <cuda_fp16.h>
#include <stdint.h>

#define IN_SIZE  4096
#define OUT_SIZE 4096
#define BATCH    256

#define BK      64                 // k-elements per stage (fp16: 128B rows)
#define NSTAGE  (IN_SIZE / BK)     // 64
#define STAGES  4
#define A_BYTES 8192               // 64 rows x 128B
#define B_BYTES 16384              // 128 rows x 128B
#define STAGE_BYTES (A_BYTES + B_BYTES)
#define SMEM_BYTES (STAGES * STAGE_BYTES)

#define ZERO_BLOCKS 8192           // 32 MB / (256 thr * 16 B)
#define CVTX_BLOCKS 1024           // 4 MB fp32 in / (256 thr * 16 B out)

// fp16 transposed weight g_Wh[out][in] — scattered into directly via f16x2 red.
__device__ __half g_Wh[(size_t)IN_SIZE * OUT_SIZE];
__device__ __half g_Xh[(size_t)BATCH * IN_SIZE];
__device__ int    g_idx_is64;

// ---------------------------------------------------------------------------
// helpers
// ---------------------------------------------------------------------------
__device__ __forceinline__ uint32_t smem_u32(const void* p) {
    uint32_t a;
    asm("{ .reg .u64 t; cvta.to.shared.u64 t, %1; cvt.u32.u64 %0, t; }"
        : "=r"(a) : "l"(p));
    return a;
}
__device__ __forceinline__ void cpa16(uint32_t s, const void* g) {
    asm volatile("cp.async.cg.shared.global [%0], [%1], 16;" :: "r"(s), "l"(g));
}
__device__ __forceinline__ void cpa_commit() {
    asm volatile("cp.async.commit_group;" ::: "memory");
}
template <int N>
__device__ __forceinline__ void cpa_wait() {
    asm volatile("cp.async.wait_group %0;" :: "n"(N) : "memory");
}
__device__ __forceinline__ void ldsm_x4(uint32_t& r0, uint32_t& r1,
                                        uint32_t& r2, uint32_t& r3, uint32_t a) {
    asm volatile("ldmatrix.sync.aligned.m8n8.x4.shared.b16 {%0,%1,%2,%3}, [%4];"
                 : "=r"(r0), "=r"(r1), "=r"(r2), "=r"(r3) : "r"(a));
}
__device__ __forceinline__ void mma_f16(float& d0, float& d1, float& d2, float& d3,
                                        uint32_t a0, uint32_t a1, uint32_t a2, uint32_t a3,
                                        uint32_t b0, uint32_t b1) {
    asm volatile(
        "mma.sync.aligned.m16n8k16.row.col.f32.f16.f16.f32 "
        "{%0,%1,%2,%3}, {%4,%5,%6,%7}, {%8,%9}, {%0,%1,%2,%3};"
        : "+f"(d0), "+f"(d1), "+f"(d2), "+f"(d3)
        : "r"(a0), "r"(a1), "r"(a2), "r"(a3), "r"(b0), "r"(b1));
}

// ---------------------------------------------------------------------------
// Prep: zero fp16 Wh (32 MB) + idx dtype detection (block 0).
// ---------------------------------------------------------------------------
__global__ void prep_kernel(const uint32_t* __restrict__ idx_words) {
    size_t i = (size_t)blockIdx.x * blockDim.x + threadIdx.x;
    reinterpret_cast<float4*>(g_Wh)[i] = make_float4(0.f, 0.f, 0.f, 0.f);
    if (blockIdx.x == 0 && threadIdx.x == 0) {
        uint32_t acc = 0;
#pragma unroll
        for (int j = 0; j < 64; ++j) acc |= idx_words[2 * j + 1];
        g_idx_is64 = (acc == 0u) ? 1 : 0;
    }
}

// ---------------------------------------------------------------------------
// Scatter: g_Wh[col][row] += fp16(val) via EXPLICIT no-return red
// (red.global.add.noftz.f16x2 on the aligned 32-bit word; neighbor lane +0.0).
// Blocks [0, CVTX_BLOCKS) convert X -> fp16 instead (independent of W).
// ---------------------------------------------------------------------------
__device__ __forceinline__ void scat1(uint32_t row, uint32_t col, float v) {
    const uint32_t cell = col * (uint32_t)IN_SIZE + row;
    uint32_t hv = (uint32_t)__half_as_ushort(__float2half_rn(v));
    hv <<= (cell & 1u) << 4;
    asm volatile("red.global.add.noftz.f16x2 [%0], %1;"
                 :: "l"(reinterpret_cast<__half2*>(g_Wh) + (cell >> 1)), "r"(hv)
                 : "memory");
}

__global__ void scatter_cvtx_kernel(const void* __restrict__ idx,
                                    const float* __restrict__ val,
                                    const float* __restrict__ X,
                                    int nnz) {
    const int b = blockIdx.x;
    if (b < CVTX_BLOCKS) {
        size_t i = (size_t)b * blockDim.x + threadIdx.x;
        float4 v = reinterpret_cast<const float4*>(X)[i];
        __half2 h0 = __floats2half2_rn(v.x, v.y);
        __half2 h1 = __floats2half2_rn(v.z, v.w);
        reinterpret_cast<__half2*>(g_Xh)[2 * i + 0] = h0;
        reinterpret_cast<__half2*>(g_Xh)[2 * i + 1] = h1;
        return;
    }

    const int base = ((b - CVTX_BLOCKS) * blockDim.x + threadIdx.x) * 8;
    if (base >= nnz) return;
    const int is64 = g_idx_is64;

    if (base + 8 <= nnz) {
        float4 va = *reinterpret_cast<const float4*>(val + base);
        float4 vb = *reinterpret_cast<const float4*>(val + base + 4);
        float v[8] = {va.x, va.y, va.z, va.w, vb.x, vb.y, vb.z, vb.w};
        uint32_t row[8], col[8];
        if (is64) {
            const longlong2* p = reinterpret_cast<const longlong2*>(idx) + base;
#pragma unroll
            for (int j = 0; j < 8; ++j) {
                longlong2 e = p[j];
                row[j] = (uint32_t)e.x;
                col[j] = (uint32_t)e.y;
            }
        } else {
            const int4* p = reinterpret_cast<const int4*>(idx) + base / 2;
#pragma unroll
            for (int j = 0; j < 4; ++j) {
                int4 e = p[j];
                row[2 * j]     = (uint32_t)e.x; col[2 * j]     = (uint32_t)e.y;
                row[2 * j + 1] = (uint32_t)e.z; col[2 * j + 1] = (uint32_t)e.w;
            }
        }
#pragma unroll
        for (int j = 0; j < 8; ++j) scat1(row[j], col[j], v[j]);
    } else {
        for (int i = base; i < nnz; ++i) {
            uint32_t row, col;
            if (is64) {
                longlong2 p = reinterpret_cast<const longlong2*>(idx)[i];
                row = (uint32_t)p.x; col = (uint32_t)p.y;
            } else {
                int2 p = reinterpret_cast<const int2*>(idx)[i];
                row = (uint32_t)p.x; col = (uint32_t)p.y;
            }
            scat1(row, col, val[i]);
        }
    }
}

// ---------------------------------------------------------------------------
// fp16 mma.sync GEMM (validated): out = relu(X @ Wh^T + bias)
// CTA 64x128, 128 threads = 4 warps (2m x 2n), warp tile 32x64.
// m16n8k16, K staged 64/iter, 64 stages, 4-stage cp.async pipeline.
// ---------------------------------------------------------------------------
__global__ __launch_bounds__(128, 1)
void gemm_f16_mma(const float* __restrict__ bias, float* __restrict__ out) {
    extern __shared__ uint32_t smu[];
    const uint32_t sbase0 = smem_u32(smu);

    const int tid   = threadIdx.x;
    const int lane  = tid & 31;
    const int wid   = tid >> 5;
    const int warpm = wid & 1;
    const int warpn = wid >> 1;
    const int m0 = blockIdx.y * 64;
    const int n0 = blockIdx.x * 128;

    const int srow = tid >> 3;
    const int sj   = tid & 7;

    const __half* Ag = g_Xh + (size_t)(m0 + srow) * IN_SIZE + sj * 8;
    const __half* Bg = g_Wh + (size_t)(n0 + srow) * IN_SIZE + sj * 8;

    const uint32_t swz = (uint32_t)((sj ^ (srow & 7)) << 4);
    uint32_t offA[4], offB[8];
#pragma unroll
    for (int i = 0; i < 4; ++i)
        offA[i] = (uint32_t)((srow + 16 * i) * 128) + swz;
#pragma unroll
    for (int i = 0; i < 8; ++i)
        offB[i] = A_BYTES + (uint32_t)((srow + 16 * i) * 128) + swz;

    const int l7 = lane & 7;
    const int qa = lane >> 4;
    const int qb = (lane >> 3) & 1;
    uint32_t rAbase[2];
#pragma unroll
    for (int msub = 0; msub < 2; ++msub)
        rAbase[msub] = (uint32_t)((warpm * 32 + msub * 16 +
                                   ((lane >> 3) & 1) * 8 + l7) * 128);
    uint32_t rBbase[4];
#pragma unroll
    for (int p = 0; p < 4; ++p)
        rBbase[p] = (uint32_t)((warpn * 64 + p * 16 + ((lane >> 4) << 3) + l7) * 128);

    float acc[2][8][4];
#pragma unroll
    for (int a = 0; a < 2; ++a)
#pragma unroll
        for (int b = 0; b < 8; ++b)
#pragma unroll
            for (int d = 0; d < 4; ++d) acc[a][b][d] = 0.f;

#pragma unroll
    for (int ps = 0; ps < 3; ++ps) {
        const uint32_t sb = sbase0 + (uint32_t)ps * STAGE_BYTES;
#pragma unroll
        for (int i = 0; i < 4; ++i)
            cpa16(sb + offA[i], Ag + (size_t)(16 * i) * IN_SIZE + ps * BK);
#pragma unroll
        for (int i = 0; i < 8; ++i)
            cpa16(sb + offB[i], Bg + (size_t)(16 * i) * IN_SIZE + ps * BK);
        cpa_commit();
    }

    for (int s = 0; s < NSTAGE; ++s) {
        cpa_wait<2>();
        __syncthreads();

        if (s + 3 < NSTAGE) {
            const uint32_t nb = sbase0 + (uint32_t)((s + 3) & 3) * STAGE_BYTES;
            const int ko = (s + 3) * BK;
#pragma unroll
            for (int i = 0; i < 4; ++i)
                cpa16(nb + offA[i], Ag + (size_t)(16 * i) * IN_SIZE + ko);
#pragma unroll
            for (int i = 0; i < 8; ++i)
                cpa16(nb + offB[i], Bg + (size_t)(16 * i) * IN_SIZE + ko);
        }
        cpa_commit();

        const uint32_t sb = sbase0 + (uint32_t)(s & 3) * STAGE_BYTES;
#pragma unroll
        for (int ks = 0; ks < 4; ++ks) {
            const uint32_t aswz = (uint32_t)(((ks * 2 + qa) ^ l7) << 4);
            const uint32_t bswz = (uint32_t)(((ks * 2 + qb) ^ l7) << 4);
            uint32_t af[2][4];
#pragma unroll
            for (int msub = 0; msub < 2; ++msub)
                ldsm_x4(af[msub][0], af[msub][1], af[msub][2], af[msub][3],
                        sb + rAbase[msub] + aswz);
            uint32_t bf[8][2];
#pragma unroll
            for (int p = 0; p < 4; ++p)
                ldsm_x4(bf[2 * p][0], bf[2 * p][1], bf[2 * p + 1][0], bf[2 * p + 1][1],
                        sb + A_BYTES + rBbase[p] + bswz);
#pragma unroll
            for (int msub = 0; msub < 2; ++msub)
#pragma unroll
                for (int nsub = 0; nsub < 8; ++nsub)
                    mma_f16(acc[msub][nsub][0], acc[msub][nsub][1],
                            acc[msub][nsub][2], acc[msub][nsub][3],
                            af[msub][0], af[msub][1], af[msub][2], af[msub][3],
                            bf[nsub][0], bf[nsub][1]);
        }
    }

#pragma unroll
    for (int msub = 0; msub < 2; ++msub) {
        const int m = m0 + warpm * 32 + msub * 16 + (lane >> 2);
#pragma unroll
        for (int nsub = 0; nsub < 8; ++nsub) {
            const int n = n0 + warpn * 64 + nsub * 8 + (lane & 3) * 2;
            float2 bv = *reinterpret_cast<const float2*>(bias + n);
            float2 o0, o1;
            o0.x = fmaxf(acc[msub][nsub][0] + bv.x, 0.f);
            o0.y = fmaxf(acc[msub][nsub][1] + bv.y, 0.f);
            o1.x = fmaxf(acc[msub][nsub][2] + bv.x, 0.f);
            o1.y = fmaxf(acc[msub][nsub][3] + bv.y, 0.f);
            *reinterpret_cast<float2*>(out + (size_t)m * OUT_SIZE + n)       = o0;
            *reinterpret_cast<float2*>(out + (size_t)(m + 8) * OUT_SIZE + n) = o1;
        }
    }
}

// ---------------------------------------------------------------------------
// kernel_launch
// ---------------------------------------------------------------------------
extern "C" void kernel_launch(void* const* d_in, const int* in_sizes, int n_in,
                              void* d_out, int out_size) {
    const float* X    = (const float*)d_in[0];
    const void*  idx  = d_in[1];
    const float* val  = (const float*)d_in[2];
    const float* bias = (const float*)d_in[3];
    float*       out  = (float*)d_out;

    const int nnz = in_sizes[2];

    prep_kernel<<<ZERO_BLOCKS, 256>>>((const uint32_t*)idx);
    const int scat_blocks = (nnz / 8 + 255) / 256;
    scatter_cvtx_kernel<<<CVTX_BLOCKS + scat_blocks, 256>>>(idx, val, X, nnz);

    cudaFuncSetAttribute(gemm_f16_mma,
                         cudaFuncAttributeMaxDynamicSharedMemorySize, SMEM_BYTES);
    dim3 grid(OUT_SIZE / 128, BATCH / 64);   // (32, 4) = 128 CTAs
    gemm_f16_mma<<<grid, 128, SMEM_BYTES>>>(bias, out);
}